// round 17
// baseline (speedup 1.0000x reference)
#include <cuda_runtime.h>
#include <cuda_fp16.h>
#include <cstdint>

#define NODE_NUM 100000
#define BATCH 4096
#define LAYERS 4
#define EMB 128
#define FEAT 256
#define NEIGH 32
#define PAIRS (BATCH*LAYERS)   // 16384

typedef unsigned long long u64;

// Scratch (device globals: allocation-free rule)
__device__ __align__(16) __half g_featsh[NODE_NUM * FEAT];  // 51.2 MB
__device__ __align__(16) __half g_sumfh[PAIRS * FEAT];      // 8 MB
__device__ __align__(16) float  g_h[PAIRS * EMB];           // 8 MB (fp32 h)
__device__ __align__(16) float  g_scores[PAIRS];            // 64 KB
__device__ __align__(16) __half g_neth[LAYERS * FEAT * EMB];// 256 KB
__device__ __align__(16) __half g_ws1h[EMB * EMB];          // 32 KB

// ---------------------------------------------------------------------------
// helpers
// ---------------------------------------------------------------------------
__device__ __forceinline__ uint32_t s2u(const void* p) {
    return (uint32_t)__cvta_generic_to_shared(p);
}
__device__ __forceinline__ void ldm4(uint32_t& r0, uint32_t& r1, uint32_t& r2,
                                     uint32_t& r3, uint32_t addr) {
    asm volatile("ldmatrix.sync.aligned.m8n8.x4.shared.b16 {%0,%1,%2,%3},[%4];"
                 : "=r"(r0), "=r"(r1), "=r"(r2), "=r"(r3) : "r"(addr));
}
__device__ __forceinline__ void ldm4t(uint32_t& r0, uint32_t& r1, uint32_t& r2,
                                      uint32_t& r3, uint32_t addr) {
    asm volatile("ldmatrix.sync.aligned.m8n8.x4.trans.shared.b16 {%0,%1,%2,%3},[%4];"
                 : "=r"(r0), "=r"(r1), "=r"(r2), "=r"(r3) : "r"(addr));
}
__device__ __forceinline__ void mma16816(float* c, uint32_t a0, uint32_t a1,
                                         uint32_t a2, uint32_t a3,
                                         uint32_t b0, uint32_t b1) {
    asm volatile(
        "mma.sync.aligned.m16n8k16.row.col.f32.f16.f16.f32 "
        "{%0,%1,%2,%3},{%4,%5,%6,%7},{%8,%9},{%0,%1,%2,%3};"
        : "+f"(c[0]), "+f"(c[1]), "+f"(c[2]), "+f"(c[3])
        : "r"(a0), "r"(a1), "r"(a2), "r"(a3), "r"(b0), "r"(b1));
}
__device__ __forceinline__ uint32_t h2u(float a, float b) {
    __half2 h = __floats2half2_rn(a, b);
    return *(uint32_t*)&h;
}
__device__ __forceinline__ u64 pack2(float x) {
    u64 r; asm("mov.b64 %0,{%1,%1};" : "=l"(r) : "f"(x)); return r;
}
__device__ __forceinline__ u64 fma2(u64 a, u64 b, u64 c) {
    u64 d; asm("fma.rn.f32x2 %0,%1,%2,%3;" : "=l"(d) : "l"(a), "l"(b), "l"(c)); return d;
}
__device__ __forceinline__ float2 unpk(u64 v) {
    float lo, hi; asm("mov.b64 {%0,%1},%2;" : "=f"(lo), "=f"(hi) : "l"(v));
    return make_float2(lo, hi);
}

// ---------------------------------------------------------------------------
// K0: convert features + net + Ws1 fp32 -> fp16 in one grid-stride kernel.
// ---------------------------------------------------------------------------
__global__ __launch_bounds__(256) void k0_all(const float* __restrict__ feats,
                                              const float* __restrict__ net,
                                              const float* __restrict__ ws1) {
    const int stride = gridDim.x * blockDim.x;
    const int F4 = NODE_NUM * FEAT / 4;          // 6,400,000
    const int N4 = LAYERS * FEAT * EMB / 4;      // 32,768
    const int W4 = EMB * EMB / 4;                // 4,096
    const int total = F4 + N4 + W4;
    for (int k = blockIdx.x * blockDim.x + threadIdx.x; k < total; k += stride) {
        float4 v; uint2 o;
        if (k < F4) {
            v = ((const float4*)feats)[k];
            o.x = h2u(v.x, v.y); o.y = h2u(v.z, v.w);
            ((uint2*)g_featsh)[k] = o;
        } else if (k < F4 + N4) {
            const int u = k - F4;
            v = ((const float4*)net)[u];
            o.x = h2u(v.x, v.y); o.y = h2u(v.z, v.w);
            ((uint2*)g_neth)[u] = o;
        } else {
            const int u = k - F4 - N4;
            v = ((const float4*)ws1)[u];
            o.x = h2u(v.x, v.y); o.y = h2u(v.z, v.w);
            ((uint2*)g_ws1h)[u] = o;
        }
    }
}

// ---------------------------------------------------------------------------
// K1: fp16 gather + sum (fp32 accum), stores fp16 sumfeat. Warp per pair.
// ---------------------------------------------------------------------------
__global__ __launch_bounds__(256) void k1_gather_h(const int* __restrict__ neighs) {
    const int tid  = threadIdx.x;
    const int warp = tid >> 5, lane = tid & 31;
    const int p = blockIdx.x * 8 + warp;
    const int myidx = neighs[p * 32 + lane];
    const float4* __restrict__ base = (const float4*)g_featsh;

    float acc[8];
    #pragma unroll
    for (int q = 0; q < 8; q++) acc[q] = 0.f;

    #pragma unroll
    for (int j = 0; j < NEIGH; j++) {
        const int n = __shfl_sync(0xffffffffu, myidx, j);
        const float4 v = base[n * 32 + lane];
        const half2* h2 = (const half2*)&v;
        #pragma unroll
        for (int q = 0; q < 4; q++) {
            const float2 f = __half22float2(h2[q]);
            acc[2 * q]     += f.x;
            acc[2 * q + 1] += f.y;
        }
    }
    uint4 o;
    o.x = h2u(acc[0], acc[1]); o.y = h2u(acc[2], acc[3]);
    o.z = h2u(acc[4], acc[5]); o.w = h2u(acc[6], acc[7]);
    *(uint4*)&g_sumfh[p * FEAT + lane * 8] = o;
}

// ---------------------------------------------------------------------------
// K2: per-layer GEMM h = sumfeat @ W_l (HMMA, register double-buffered) PLUS
// in-block scores GEMM: scores = tanh(h @ Ws1) . Ws2 -> g_scores.
// grid (64, 4). block 256 (8 warps). M=64, N=128, K=256.
// ---------------------------------------------------------------------------
__global__ __launch_bounds__(256) void k2_gemm(const float* __restrict__ Ws2) {
    __shared__ __align__(16) unsigned char SB[27648];
    __half (*Ah)[72]  = (__half(*)[72])(SB + 0);
    __half (*Bh)[136] = (__half(*)[136])(SB + 9216);
    __half (*Ws)[136] = (__half(*)[136])(SB + 0);
    __half (*Hs)[136] = (__half(*)[136])(SB + 9216);
    float  *w2s       = (float*)(SB + 26624);
    float (*red)[2]   = (float(*)[2])(SB + 27136);

    const int l  = blockIdx.y;
    const int bm = blockIdx.x;
    const int tid = threadIdx.x;
    const int w = tid >> 5, lane = tid & 31;
    const int m0 = (w & 3) * 16;
    const int nh = w >> 2;
    const int n0 = nh * 64;
    const int lq = lane >> 3, lr = lane & 7;
    const int g = lane >> 2, t = lane & 3;

    if (tid < 128) w2s[tid] = Ws2[tid];

    // staging indices
    const int uA0 = tid,        rA0 = uA0 >> 3, cA0 = uA0 & 7;
    const int uA1 = tid + 256,  rA1 = uA1 >> 3, cA1 = uA1 & 7;
    int rB[4], cB[4];
    #pragma unroll
    for (int i = 0; i < 4; i++) {
        const int u = tid + i * 256;
        rB[i] = u >> 4; cB[i] = u & 15;
    }
    const int pairA0 = (bm * 64 + rA0) * 4 + l;
    const int pairA1 = (bm * 64 + rA1) * 4 + l;
    const __half* __restrict__ netl = g_neth + l * FEAT * EMB;

    float acc[8][4];
    #pragma unroll
    for (int i = 0; i < 8; i++)
        #pragma unroll
        for (int j = 0; j < 4; j++) acc[i][j] = 0.f;

    uint4 pA0, pA1, pB[4];
    pA0 = *(const uint4*)&g_sumfh[pairA0 * FEAT + cA0 * 8];
    pA1 = *(const uint4*)&g_sumfh[pairA1 * FEAT + cA1 * 8];
    #pragma unroll
    for (int i = 0; i < 4; i++)
        pB[i] = *(const uint4*)&netl[rB[i] * EMB + cB[i] * 8];
    *(uint4*)&Ah[rA0][cA0 * 8] = pA0;
    *(uint4*)&Ah[rA1][cA1 * 8] = pA1;
    #pragma unroll
    for (int i = 0; i < 4; i++) *(uint4*)&Bh[rB[i]][cB[i] * 8] = pB[i];
    __syncthreads();

    for (int c = 0; c < 4; c++) {
        if (c < 3) {
            const int kb = (c + 1) * 64;
            pA0 = *(const uint4*)&g_sumfh[pairA0 * FEAT + kb + cA0 * 8];
            pA1 = *(const uint4*)&g_sumfh[pairA1 * FEAT + kb + cA1 * 8];
            #pragma unroll
            for (int i = 0; i < 4; i++)
                pB[i] = *(const uint4*)&netl[(kb + rB[i]) * EMB + cB[i] * 8];
        }
        #pragma unroll
        for (int ks = 0; ks < 4; ks++) {
            const int kc = ks * 16;
            uint32_t a0, a1, a2, a3;
            ldm4(a0, a1, a2, a3,
                 s2u(&Ah[m0 + lr + (lq & 1) * 8][kc + (lq >> 1) * 8]));
            #pragma unroll
            for (int jn = 0; jn < 4; jn++) {
                uint32_t b0, b1, b2, b3;
                ldm4t(b0, b1, b2, b3,
                      s2u(&Bh[kc + lr + (lq & 1) * 8][n0 + jn * 16 + (lq >> 1) * 8]));
                mma16816(acc[2 * jn],     a0, a1, a2, a3, b0, b1);
                mma16816(acc[2 * jn + 1], a0, a1, a2, a3, b2, b3);
            }
        }
        __syncthreads();
        if (c < 3) {
            *(uint4*)&Ah[rA0][cA0 * 8] = pA0;
            *(uint4*)&Ah[rA1][cA1 * 8] = pA1;
            #pragma unroll
            for (int i = 0; i < 4; i++) *(uint4*)&Bh[rB[i]][cB[i] * 8] = pB[i];
            __syncthreads();
        }
    }

    // epilogue A: write fp32 h to global, fp16 h to smem Hs (alias Bh)
    #pragma unroll
    for (int jn2 = 0; jn2 < 8; jn2++) {
        const int col = n0 + jn2 * 8 + 2 * t;
        const int row0 = m0 + g;
        const int gp0 = (bm * 64 + row0) * 4 + l;
        const int gp1 = (bm * 64 + row0 + 8) * 4 + l;
        *(float2*)&g_h[gp0 * EMB + col] = make_float2(acc[jn2][0], acc[jn2][1]);
        *(float2*)&g_h[gp1 * EMB + col] = make_float2(acc[jn2][2], acc[jn2][3]);
        *(uint32_t*)&Hs[row0][col]     = h2u(acc[jn2][0], acc[jn2][1]);
        *(uint32_t*)&Hs[row0 + 8][col] = h2u(acc[jn2][2], acc[jn2][3]);
    }
    __syncthreads();

    // scores GEMM: Hs[64x128] @ Ws1[128x128], K chunks of 32 (Ws aliases Ah)
    float acc2s[8][4];
    #pragma unroll
    for (int i = 0; i < 8; i++)
        #pragma unroll
        for (int j = 0; j < 4; j++) acc2s[i][j] = 0.f;

    for (int ch = 0; ch < 4; ch++) {
        #pragma unroll
        for (int i = 0; i < 4; i++) {
            const int idx = tid + i * 256;
            const int row = idx >> 5, c4 = idx & 31;
            *(uint2*)&Ws[row][c4 * 4] =
                *(const uint2*)&g_ws1h[(ch * 32 + row) * EMB + c4 * 4];
        }
        __syncthreads();
        #pragma unroll
        for (int ks = 0; ks < 2; ks++) {
            const int kc = ks * 16;
            uint32_t a0, a1, a2, a3;
            ldm4(a0, a1, a2, a3,
                 s2u(&Hs[m0 + lr + (lq & 1) * 8][ch * 32 + kc + (lq >> 1) * 8]));
            #pragma unroll
            for (int jn = 0; jn < 4; jn++) {
                uint32_t b0, b1, b2, b3;
                ldm4t(b0, b1, b2, b3,
                      s2u(&Ws[kc + lr + (lq & 1) * 8][n0 + jn * 16 + (lq >> 1) * 8]));
                mma16816(acc2s[2 * jn],     a0, a1, a2, a3, b0, b1);
                mma16816(acc2s[2 * jn + 1], a0, a1, a2, a3, b2, b3);
            }
        }
        __syncthreads();
    }
    // epilogue B: tanh + dot with Ws2, quad reduce, write g_scores
    {
        float p0 = 0.f, p1 = 0.f;
        #pragma unroll
        for (int jn2 = 0; jn2 < 8; jn2++) {
            const int col = n0 + jn2 * 8 + 2 * t;
            p0 += tanhf(acc2s[jn2][0]) * w2s[col] + tanhf(acc2s[jn2][1]) * w2s[col + 1];
            p1 += tanhf(acc2s[jn2][2]) * w2s[col] + tanhf(acc2s[jn2][3]) * w2s[col + 1];
        }
        p0 += __shfl_xor_sync(0xffffffffu, p0, 1);
        p0 += __shfl_xor_sync(0xffffffffu, p0, 2);
        p1 += __shfl_xor_sync(0xffffffffu, p1, 1);
        p1 += __shfl_xor_sync(0xffffffffu, p1, 2);
        if (t == 0) {
            red[m0 + g][nh]     = p0;
            red[m0 + 8 + g][nh] = p1;
        }
    }
    __syncthreads();
    if (tid < 64)
        g_scores[(bm * 64 + tid) * 4 + l] = red[tid][0] + red[tid][1];
}

// ---------------------------------------------------------------------------
// K34 (slim): softmax + agg + agg@TW + residual + normalize.
// tile = 16 batch rows (64 pairs), grid 256 blocks, 256 threads.
// ---------------------------------------------------------------------------
__global__ __launch_bounds__(256) void k34_fused(const float* __restrict__ TW,
                                                 const float* __restrict__ lemb,
                                                 const int* __restrict__ node_i,
                                                 const int* __restrict__ layers,
                                                 float* __restrict__ out) {
    __shared__ __align__(16) unsigned char SB[43008];
    float (*Bs4)[132]  = (float(*)[132])(SB + 0);        // 33792 (TW chunks)
    float (*aggs)[132] = (float(*)[132])(SB + 33792);    // 8448 -> 42240
    float (*att)[4]    = (float(*)[4])(SB + 42240);      // 256
    float (*red)[2]    = (float(*)[2])(SB + 42496);      // 512

    const int tid = threadIdx.x;
    const int bm = blockIdx.x;
    const int pb = bm * 64;
    const int B0 = bm * 16;
    const int w = tid >> 5, lane = tid & 31;

    // ---- softmax over 4 layers (16 rows) ----
    if (tid < 16) {
        const int base = (B0 + tid) * 4;
        const float s0 = g_scores[base + 0];
        const float s1 = g_scores[base + 1];
        const float s2 = g_scores[base + 2];
        const float s3 = g_scores[base + 3];
        const float mx = fmaxf(fmaxf(s0, s1), fmaxf(s2, s3));
        const float e0 = __expf(s0 - mx), e1 = __expf(s1 - mx);
        const float e2 = __expf(s2 - mx), e3 = __expf(s3 - mx);
        const float inv = 1.f / (e0 + e1 + e2 + e3);
        att[tid][0] = e0 * inv; att[tid][1] = e1 * inv;
        att[tid][2] = e2 * inv; att[tid][3] = e3 * inv;
    }
    __syncthreads();

    // ---- agg (float4 vectorized) ----
    {
        const int m4 = tid & 31;
        const int bh = tid >> 5;
        #pragma unroll
        for (int bb = 0; bb < 2; bb++) {
            const int b = bh * 2 + bb;
            const float4* hp = (const float4*)&g_h[(pb + b * 4) * EMB];
            const float4 v0 = hp[m4];
            const float4 v1 = hp[32 + m4];
            const float4 v2 = hp[64 + m4];
            const float4 v3 = hp[96 + m4];
            const float a0 = att[b][0], a1 = att[b][1];
            const float a2 = att[b][2], a3 = att[b][3];
            float4 r;
            r.x = fmaf(a3, v3.x, fmaf(a2, v2.x, fmaf(a1, v1.x, a0 * v0.x)));
            r.y = fmaf(a3, v3.y, fmaf(a2, v2.y, fmaf(a1, v1.y, a0 * v0.y)));
            r.z = fmaf(a3, v3.z, fmaf(a2, v2.z, fmaf(a1, v1.z, a0 * v0.z)));
            r.w = fmaf(a3, v3.w, fmaf(a2, v2.w, fmaf(a1, v1.w, a0 * v0.w)));
            *(float4*)&aggs[b][m4 * 4] = r;
        }
    }
    __syncthreads();

    // ---- ne = agg @ TW via shuffle-fed FFMA2 ----
    const int rg = w >> 1;
    const int cg = w & 1;
    u64 acc2[4];
    #pragma unroll
    for (int r = 0; r < 4; r++) acc2[r] = 0ull;

    for (int ch = 0; ch < 2; ch++) {
        #pragma unroll
        for (int i = 0; i < 32; i++) {
            const int idx = tid + i * 256;
            const int f = idx >> 7, m = idx & 127;
            Bs4[f][m] = TW[(ch * 64 + f) * EMB + m];
        }
        __syncthreads();
        #pragma unroll
        for (int w0 = 0; w0 < 64; w0 += 32) {
            float aw0 = aggs[rg * 4 + 0][ch * 64 + w0 + lane];
            float aw1 = aggs[rg * 4 + 1][ch * 64 + w0 + lane];
            float aw2 = aggs[rg * 4 + 2][ch * 64 + w0 + lane];
            float aw3 = aggs[rg * 4 + 3][ch * 64 + w0 + lane];
            #pragma unroll
            for (int kk = 0; kk < 32; kk++) {
                const u64 wv = *(const u64*)&Bs4[w0 + kk][cg * 64 + lane * 2];
                const float a0 = __shfl_sync(0xffffffffu, aw0, kk);
                const float a1 = __shfl_sync(0xffffffffu, aw1, kk);
                const float a2 = __shfl_sync(0xffffffffu, aw2, kk);
                const float a3 = __shfl_sync(0xffffffffu, aw3, kk);
                acc2[0] = fma2(pack2(a0), wv, acc2[0]);
                acc2[1] = fma2(pack2(a1), wv, acc2[1]);
                acc2[2] = fma2(pack2(a2), wv, acc2[2]);
                acc2[3] = fma2(pack2(a3), wv, acc2[3]);
            }
        }
        __syncthreads();
    }

    // ---- residual + L2 normalize ----
    float2 fv[4];
    #pragma unroll
    for (int r = 0; r < 4; r++) {
        const int bg = B0 + rg * 4 + r;
        const int li = node_i[bg] * 4 + layers[bg];
        const float2 lv = *(const float2*)&lemb[li * EMB + cg * 64 + lane * 2];
        const float2 f2 = unpk(acc2[r]);
        fv[r].x = f2.x + lv.x;
        fv[r].y = f2.y + lv.y;
        float v = fv[r].x * fv[r].x + fv[r].y * fv[r].y;
        #pragma unroll
        for (int off = 16; off > 0; off >>= 1)
            v += __shfl_xor_sync(0xffffffffu, v, off);
        if (lane == 0) red[rg * 4 + r][cg] = v;
    }
    __syncthreads();
    #pragma unroll
    for (int r = 0; r < 4; r++) {
        const int bg = B0 + rg * 4 + r;
        const float nrm = sqrtf(red[rg * 4 + r][0] + red[rg * 4 + r][1]);
        const float inv = 1.f / fmaxf(nrm, 1e-12f);
        float2 o;
        o.x = fv[r].x * inv; o.y = fv[r].y * inv;
        *(float2*)&out[bg * EMB + cg * 64 + lane * 2] = o;
    }
}

// ---------------------------------------------------------------------------
extern "C" void kernel_launch(void* const* d_in, const int* in_sizes, int n_in,
                              void* d_out, int out_size) {
    const int*   layers  = (const int*)d_in[0];
    const int*   node_i  = (const int*)d_in[1];
    const int*   neighs  = (const int*)d_in[2];
    const float* feats   = (const float*)d_in[3];
    const float* lemb    = (const float*)d_in[4];
    const float* net     = (const float*)d_in[5];
    const float* TW      = (const float*)d_in[6];
    const float* Ws1     = (const float*)d_in[7];
    const float* Ws2     = (const float*)d_in[8];
    float* out = (float*)d_out;

    k0_all<<<2048, 256>>>(feats, net, Ws1);
    k1_gather_h<<<PAIRS / 8, 256>>>(neighs);
    k2_gemm<<<dim3(BATCH / 64, LAYERS), 256>>>(Ws2);
    k34_fused<<<PAIRS / 64, 256>>>(TW, lemb, node_i, layers, out);
}